// round 5
// baseline (speedup 1.0000x reference)
#include <cuda_runtime.h>
#include <cuda_fp16.h>
#include <cstdint>

#define NMAX 50000
#define EMAX 1600000
#define RECF 12   // floats per CSR record: src,e0,e1,pad -> actually 12: src,e0,e1, 8x half2, pad
#define NTYPES 20
#define MAXB (NMAX / 256 + NTYPES + 2)

// ---------------- scratch (static __device__, no allocations) ----------------
__device__ float  g_hm[NMAX * 32];            // h @ lin_W[0:32] per node (6.4MB, L2-resident)
__device__ float2 g_ai[NMAX];                 // h @ att_W[0:32]  (dst term)
__device__ float2 g_aj[NMAX];                 // h @ att_W[32:64] (src term)
__device__ float  g_rec[(size_t)EMAX * RECF]; // CSR records (76.8MB)
__device__ unsigned g_rank[EMAX];             // packed (copy<<28)|rank per edge
__device__ int    g_cnt4[4 * NMAX];           // split histogram -> per-copy CSR bases
__device__ int    g_cnt[NMAX];
__device__ int    g_scan[NMAX];
__device__ int    g_rowptr[NMAX];
__device__ int    g_bsum[128];
__device__ float  g_ae[8];                    // lrelu(etype_table) @ att_W[64:80]
__device__ int    g_tcnt[NTYPES];             // per-ntype node counts
__device__ int    g_perm[NTYPES * NMAX];      // node buckets by type
__device__ int    g_btab[MAXB];               // block table: (type<<16)|chunk
__device__ int    g_nbk;                      // number of node blocks

__device__ __forceinline__ float lrelu(float v) { return v > 0.f ? v : 0.2f * v; }

// ---------------- K0: zero counters ----------------
__global__ void k_z0(int n) {
    int i = blockIdx.x * 1024 + threadIdx.x;
    if (i < 4 * n) g_cnt4[i] = 0;
    if (i < NTYPES) g_tcnt[i] = 0;
}

// ---------------- K1: bucket nodes by type ----------------
__global__ void k_bucket(const int* __restrict__ ntypes, int n) {
    int i = blockIdx.x * 256 + threadIdx.x;
    if (i < n) {
        int t = ntypes[i];
        int pos = atomicAdd(&g_tcnt[t], 1);
        g_perm[t * NMAX + pos] = i;
    }
}

// ---------------- K2: build block table (1 warp) + ae term ----------------
__global__ void k_btab(const float* __restrict__ ett, const float* __restrict__ attW) {
    int tid = threadIdx.x;
    if (tid < 32) {
        int nb = 0;
        if (tid < NTYPES) nb = (g_tcnt[tid] + 255) >> 8;
        // exclusive scan over 32 lanes
        int excl = nb;
#pragma unroll
        for (int off = 1; off < 32; off <<= 1) {
            int v = __shfl_up_sync(0xffffffffu, excl, off);
            if (tid >= off) excl += v;
        }
        excl -= nb;  // exclusive
        if (tid < NTYPES) {
            for (int j = 0; j < nb; ++j)
                g_btab[excl + j] = (tid << 16) | j;
        }
        int total = excl + nb;
        if (tid == NTYPES - 1) g_nbk = total;
    } else if (tid >= 32 && tid < 40) {
        int q = tid - 32;
        int t = q >> 1, hh = q & 1;
        float s = 0.f;
        for (int k = 0; k < 16; ++k)
            s += lrelu(ett[t * 16 + k]) * attW[(64 + k) * 2 + hh];
        g_ae[q] = s;
    }
}

// ---------------- K3: node compute, type-bucketed, smem-staged weights ----------------
__global__ __launch_bounds__(256) void k_node2(
    const float* __restrict__ x,
    const float* __restrict__ hetW, const float* __restrict__ hetB,
    const float* __restrict__ attW, const float* __restrict__ linW)
{
    __shared__ float sW[4096];    // hetW[t]: [128,32]
    __shared__ float slin[1024];  // lin_W rows 0..31: [32,32]
    __shared__ float sat[128];    // att_W rows 0..63: [64,2]
    __shared__ float sB[32];      // hetB[t]

    int b = blockIdx.x;
    if (b >= g_nbk) return;
    int packed = g_btab[b];
    int t = packed >> 16;
    int start = (packed & 0xFFFF) * 256;
    int tid = threadIdx.x;

    const float4* wsrc = (const float4*)(hetW + (size_t)t * 4096);
    for (int q = tid; q < 1024; q += 256) ((float4*)sW)[q] = wsrc[q];
    if (tid < 256) ((float4*)slin)[tid] = ((const float4*)linW)[tid];
    if (tid < 32) {
        ((float4*)sat)[tid] = ((const float4*)attW)[tid];
        sB[tid] = hetB[t * 32 + tid];
    }
    __syncthreads();

    int pos = start + tid;
    if (pos >= g_tcnt[t]) return;
    int node = g_perm[t * NMAX + pos];

    float h[32];
#pragma unroll
    for (int k = 0; k < 32; ++k) h[k] = sB[k];

    const float4* xp = (const float4*)(x + (size_t)node * 128);
#pragma unroll 4
    for (int d4 = 0; d4 < 32; ++d4) {
        float4 xq = xp[d4];
        float xv[4] = {xq.x, xq.y, xq.z, xq.w};
#pragma unroll
        for (int j = 0; j < 4; ++j) {
            const float* wr = &sW[(d4 * 4 + j) * 32];
            float v = xv[j];
#pragma unroll
            for (int k = 0; k < 32; ++k) h[k] += v * wr[k];
        }
    }

    // attention partials
    float ai0 = 0.f, ai1 = 0.f, aj0 = 0.f, aj1 = 0.f;
#pragma unroll
    for (int k = 0; k < 32; ++k) {
        ai0 += h[k] * sat[2 * k];
        ai1 += h[k] * sat[2 * k + 1];
        aj0 += h[k] * sat[64 + 2 * k];
        aj1 += h[k] * sat[64 + 2 * k + 1];
    }
    g_ai[node] = make_float2(ai0, ai1);
    g_aj[node] = make_float2(aj0, aj1);

    // hm = h @ lin_W[0:32]
    float hm[32];
#pragma unroll
    for (int c = 0; c < 32; ++c) hm[c] = 0.f;
#pragma unroll
    for (int k = 0; k < 32; ++k) {
        float v = h[k];
        const float* lr = &slin[k * 32];
#pragma unroll
        for (int c = 0; c < 32; ++c) hm[c] += v * lr[c];
    }
    float4* ho = (float4*)(g_hm + (size_t)node * 32);
#pragma unroll
    for (int c4 = 0; c4 < 8; ++c4)
        ho[c4] = make_float4(hm[4 * c4], hm[4 * c4 + 1], hm[4 * c4 + 2], hm[4 * c4 + 3]);
}

// ---------------- K4: degree histogram with rank capture ----------------
__global__ void k_cnt(const int* __restrict__ dst, int e_total, int n) {
    int i = blockIdx.x * 256 + threadIdx.x;
    unsigned c = ((threadIdx.x >> 5) & 3);
    int cb = c * n;
    int base = i * 4;
    if (base + 4 <= e_total) {
        int4 d = *(const int4*)(dst + base);
        unsigned r0 = atomicAdd(&g_cnt4[cb + d.x], 1);
        unsigned r1 = atomicAdd(&g_cnt4[cb + d.y], 1);
        unsigned r2 = atomicAdd(&g_cnt4[cb + d.z], 1);
        unsigned r3 = atomicAdd(&g_cnt4[cb + d.w], 1);
        uint4 rr = make_uint4((c << 28) | r0, (c << 28) | r1, (c << 28) | r2, (c << 28) | r3);
        *(uint4*)(g_rank + base) = rr;
    } else {
        for (int e = base; e < e_total; ++e) {
            unsigned r = atomicAdd(&g_cnt4[cb + dst[e]], 1);
            g_rank[e] = (c << 28) | r;
        }
    }
}

// ---------------- K5: scan ----------------
__global__ void k_scan1(int n) {
    __shared__ int s[1024];
    int i = blockIdx.x * 1024 + threadIdx.x;
    int v = 0;
    if (i < n) {
        v = g_cnt4[i] + g_cnt4[n + i] + g_cnt4[2 * n + i] + g_cnt4[3 * n + i];
        g_cnt[i] = v;
    }
    s[threadIdx.x] = v;
    __syncthreads();
    for (int off = 1; off < 1024; off <<= 1) {
        int t = (threadIdx.x >= off) ? s[threadIdx.x - off] : 0;
        __syncthreads();
        s[threadIdx.x] += t;
        __syncthreads();
    }
    if (i < n) g_scan[i] = s[threadIdx.x];
    if (threadIdx.x == 1023) g_bsum[blockIdx.x] = s[1023];
}
__global__ void k_scan3(int n) {
    __shared__ int soff;
    int tid = threadIdx.x;
    if (tid < 32) {
        int bid = blockIdx.x;
        int v = (tid < bid) ? g_bsum[tid] : 0;
        if (tid + 32 < bid) v += g_bsum[tid + 32];
#pragma unroll
        for (int off = 16; off; off >>= 1) v += __shfl_down_sync(0xffffffffu, v, off);
        if (tid == 0) soff = v;
    }
    __syncthreads();
    int i = blockIdx.x * 1024 + tid;
    if (i < n) {
        int c0 = g_cnt4[i], c1 = g_cnt4[n + i], c2 = g_cnt4[2 * n + i];
        int rp = g_scan[i] - g_cnt[i] + soff;
        g_rowptr[i] = rp;
        g_cnt4[i] = rp;
        g_cnt4[n + i] = rp + c0;
        g_cnt4[2 * n + i] = rp + c0 + c1;
        g_cnt4[3 * n + i] = rp + c0 + c1 + c2;
    }
}

// ---------------- K6: edge pass — ea, exp(alpha); scatter 48B record, no atomics ----------------
__global__ __launch_bounds__(256) void k_edge1(
    const int* __restrict__ ei, const int* __restrict__ etypes,
    const float* __restrict__ eattr, const float* __restrict__ cW,
    const float* __restrict__ attW, int e_total, int n)
{
    __shared__ float4 scW4[64];
    __shared__ float2 saW2[16];
    __shared__ float  sae[8];
    int tid = threadIdx.x;
    if (tid < 64) scW4[tid] = ((const float4*)cW)[tid];
    else if (tid < 80) saW2[tid - 64] = ((const float2*)(attW + 160))[tid - 64];
    else if (tid < 88) sae[tid - 80] = g_ae[tid - 80];
    __syncthreads();

    int e = blockIdx.x * 256 + tid;
    if (e >= e_total) return;
    int src = ei[e], dst = ei[e_total + e], et = etypes[e];

    const float4* er = (const float4*)(eattr + (size_t)e * 16);
    float4 q0 = er[0], q1 = er[1], q2 = er[2], q3 = er[3];
    float va[16] = {q0.x, q0.y, q0.z, q0.w, q1.x, q1.y, q1.z, q1.w,
                    q2.x, q2.y, q2.z, q2.w, q3.x, q3.y, q3.z, q3.w};

    float ea[16];
#pragma unroll
    for (int k = 0; k < 16; ++k) ea[k] = 0.f;
#pragma unroll
    for (int d = 0; d < 16; ++d) {
        float vd = va[d];
#pragma unroll
        for (int k4 = 0; k4 < 4; ++k4) {
            float4 w = scW4[d * 4 + k4];
            ea[k4 * 4 + 0] += vd * w.x;
            ea[k4 * 4 + 1] += vd * w.y;
            ea[k4 * 4 + 2] += vd * w.z;
            ea[k4 * 4 + 3] += vd * w.w;
        }
    }
#pragma unroll
    for (int k = 0; k < 16; ++k) ea[k] = lrelu(ea[k]);

    float2 fi = g_ai[dst], fj = g_aj[src];
    float a0 = fi.x + fj.x + sae[et * 2 + 0];
    float a1 = fi.y + fj.y + sae[et * 2 + 1];
#pragma unroll
    for (int k = 0; k < 16; ++k) {
        float2 w = saW2[k];
        a0 += ea[k] * w.x;
        a1 += ea[k] * w.y;
    }
    float e0 = __expf(lrelu(a0));
    float e1 = __expf(lrelu(a1));

    uint32_t u[8];
#pragma unroll
    for (int i2 = 0; i2 < 8; ++i2) {
        __half2 h = __floats2half2_rn(ea[2 * i2], ea[2 * i2 + 1]);
        u[i2] = *reinterpret_cast<uint32_t*>(&h);
    }

    unsigned pk = g_rank[e];
    int pos = g_cnt4[(pk >> 28) * n + dst] + (int)(pk & 0x0FFFFFFFu);
    float4* rp = (float4*)(g_rec + (size_t)pos * RECF);
    rp[0] = make_float4(__int_as_float(src), e0, e1, 0.f);
    rp[1] = make_float4(__uint_as_float(u[0]), __uint_as_float(u[1]),
                        __uint_as_float(u[2]), __uint_as_float(u[3]));
    rp[2] = make_float4(__uint_as_float(u[4]), __uint_as_float(u[5]),
                        __uint_as_float(u[6]), __uint_as_float(u[7]));
}

// ---------------- K7: aggregate — interleaved persistent warps ----------------
__global__ __launch_bounds__(256) void k_edge2(
    float* __restrict__ out, const float* __restrict__ linW, int n)
{
    __shared__ float slW2[512];
    __shared__ float ss0[8][32];
    __shared__ float ss1[8][32];
    int tid = threadIdx.x;
    slW2[tid] = linW[1024 + tid];
    slW2[256 + tid] = linW[1280 + tid];
    __syncthreads();

    int w = tid >> 5, lane = tid & 31;
    int wid = blockIdx.x * 8 + w;
    int W = gridDim.x * 8;

    int loff = (lane < 16) ? lane : (lane - 16) + RECF;
    bool lact = (lane & 15) < RECF;

    for (int node = wid; node < n; node += W) {
        int beg = g_rowptr[node];
        int cnt = g_cnt[node];
        const float* rb = g_rec + (size_t)beg * RECF;

        float acc0 = 0.f, acc1 = 0.f;
        float s0x = 0.f, s0y = 0.f, s1x = 0.f, s1y = 0.f;
        float den0 = 0.f, den1 = 0.f;

        int p = 0;
#pragma unroll 2
        for (; p + 2 <= cnt; p += 2) {
            float v = lact ? rb[(size_t)p * RECF + loff] : 0.f;

            int   sa = __float_as_int(__shfl_sync(0xffffffffu, v, 0));
            float a0 = __shfl_sync(0xffffffffu, v, 1);
            float a1 = __shfl_sync(0xffffffffu, v, 2);
            int   sb = __float_as_int(__shfl_sync(0xffffffffu, v, 16));
            float b0 = __shfl_sync(0xffffffffu, v, 17);
            float b1 = __shfl_sync(0xffffffffu, v, 18);

            __half2 hh = *reinterpret_cast<__half2*>(&v);
            float2 f2 = __half22float2(hh);
            float e0s = (lane < 16) ? a0 : b0;
            float e1s = (lane < 16) ? a1 : b1;
            s0x += e0s * f2.x; s0y += e0s * f2.y;
            s1x += e1s * f2.x; s1y += e1s * f2.y;

            float ha = g_hm[(size_t)sa * 32 + lane];
            float hb = g_hm[(size_t)sb * 32 + lane];
            acc0 += a0 * ha + b0 * hb;
            acc1 += a1 * ha + b1 * hb;
            den0 += a0 + b0;
            den1 += a1 + b1;
        }
        if (p < cnt) {
            float v = (lane < RECF) ? rb[(size_t)p * RECF + lane] : 0.f;
            int   sa = __float_as_int(__shfl_sync(0xffffffffu, v, 0));
            float a0 = __shfl_sync(0xffffffffu, v, 1);
            float a1 = __shfl_sync(0xffffffffu, v, 2);
            __half2 hh = *reinterpret_cast<__half2*>(&v);
            float2 f2 = __half22float2(hh);
            if (lane < 16) {
                s0x += a0 * f2.x; s0y += a0 * f2.y;
                s1x += a1 * f2.x; s1y += a1 * f2.y;
            }
            float ha = g_hm[(size_t)sa * 32 + lane];
            acc0 += a0 * ha;
            acc1 += a1 * ha;
            den0 += a0;
            den1 += a1;
        }

        if (lane >= 4 && lane < 12) {
            int d = (lane - 4) * 2;
            ss0[w][d] = s0x; ss0[w][d + 1] = s0y;
            ss1[w][d] = s1x; ss1[w][d + 1] = s1y;
        } else if (lane >= 20 && lane < 28) {
            int d = 16 + (lane - 20) * 2;
            ss0[w][d] = s0x; ss0[w][d + 1] = s0y;
            ss1[w][d] = s1x; ss1[w][d + 1] = s1y;
        }
        __syncwarp();

#pragma unroll
        for (int k = 0; k < 16; ++k) {
            float lw = slW2[k * 32 + lane];
            acc0 += (ss0[w][k] + ss0[w][16 + k]) * lw;
            acc1 += (ss1[w][k] + ss1[w][16 + k]) * lw;
        }
        __syncwarp();

        float i0 = (den0 != 0.f) ? 1.f / den0 : 0.f;
        float i1 = (den1 != 0.f) ? 1.f / den1 : 0.f;
        out[(size_t)node * 64 + lane]      = fmaxf(acc0 * i0, 0.f);
        out[(size_t)node * 64 + 32 + lane] = fmaxf(acc1 * i1, 0.f);
    }
}

// ---------------- launch ----------------
extern "C" void kernel_launch(void* const* d_in, const int* in_sizes, int n_in,
                              void* d_out, int out_size)
{
    const float* x      = (const float*)d_in[0];
    const int*   ei     = (const int*)  d_in[1];
    const int*   ntypes = (const int*)  d_in[2];
    const int*   etypes = (const int*)  d_in[3];
    const float* eattr  = (const float*)d_in[4];
    const float* hetW   = (const float*)d_in[5];
    const float* hetB   = (const float*)d_in[6];
    const float* ett    = (const float*)d_in[7];
    const float* cW     = (const float*)d_in[8];
    const float* attW   = (const float*)d_in[9];
    const float* linW   = (const float*)d_in[10];

    int n = in_sizes[0] / 128;
    int e = in_sizes[1] / 2;
    if (n > NMAX) n = NMAX;
    if (e > EMAX) e = EMAX;

    k_z0<<<(4 * n + 1023) / 1024, 1024>>>(n);
    k_bucket<<<(n + 255) / 256, 256>>>(ntypes, n);
    k_btab<<<1, 64>>>(ett, attW);
    k_node2<<<n / 256 + NTYPES + 1, 256>>>(x, hetW, hetB, attW, linW);
    k_cnt<<<((e + 3) / 4 + 255) / 256, 256>>>(ei + e, e, n);

    int nb = (n + 1023) / 1024;
    k_scan1<<<nb, 1024>>>(n);
    k_scan3<<<nb, 1024>>>(n);

    k_edge1<<<(e + 255) / 256, 256>>>(ei, etypes, eattr, cW, attW, e, n);
    k_edge2<<<592, 256>>>((float*)d_out, linW, n);
}

// round 6
// speedup vs baseline: 1.0079x; 1.0079x over previous
#include <cuda_runtime.h>
#include <cuda_fp16.h>
#include <cstdint>

#define NMAX 50000
#define EMAX 1600000
#define RECF 12   // floats per CSR record: src,e0,e1, 8x half2(ea[16]), pad

// ---------------- scratch (static __device__, no allocations) ----------------
__device__ float  g_hm[NMAX * 32];            // h @ lin_W[0:32] per node (6.4MB, L2-resident)
__device__ float2 g_ai[NMAX];                 // h @ att_W[0:32]  (dst term)
__device__ float2 g_aj[NMAX];                 // h @ att_W[32:64] (src term)
__device__ float  g_rec[(size_t)EMAX * RECF]; // CSR records (76.8MB)
__device__ unsigned g_rank[EMAX];             // packed (copy<<28)|rank per edge
__device__ int    g_cnt4[4 * NMAX];           // split histogram -> per-copy CSR bases
__device__ int    g_cnt[NMAX];
__device__ int    g_scan[NMAX];
__device__ int    g_rowptr[NMAX];
__device__ int    g_bsum[128];
__device__ float  g_ae[8];                    // lrelu(etype_table) @ att_W[64:80]

__device__ __forceinline__ float lrelu(float v) { return v > 0.f ? v : 0.2f * v; }

// ---------------- K1: node precompute (warp per node) + zero cnt4 + ae ----------------
__global__ __launch_bounds__(256) void k_node(
    const float* __restrict__ x, const int* __restrict__ ntypes,
    const float* __restrict__ hetW, const float* __restrict__ hetB,
    const float* __restrict__ attW, const float* __restrict__ linW,
    const float* __restrict__ ett, int n)
{
    __shared__ float sx[8][128];
    __shared__ float sh[8][32];
    int tid = threadIdx.x;

    // folded: zero split histogram (grid covers 4n easily)
    int z = blockIdx.x * 256 + tid;
    if (z < 4 * n) g_cnt4[z] = 0;
    // folded: per-etype attention term
    if (blockIdx.x == 0 && tid < 8) {
        int t = tid >> 1, hh = tid & 1;
        float s = 0.f;
        for (int k = 0; k < 16; ++k)
            s += lrelu(ett[t * 16 + k]) * attW[(64 + k) * 2 + hh];
        g_ae[tid] = s;
    }

    int w = tid >> 5, lane = tid & 31;
    int node = blockIdx.x * 8 + w;
    if (node >= n) return;

    const float4* xr = (const float4*)(x + (size_t)node * 128);
    ((float4*)sx[w])[lane] = xr[lane];
    __syncwarp();

    int t = ntypes[node];
    const float* Wp = hetW + (size_t)t * 4096 + lane;
    float acc = hetB[t * 32 + lane];
#pragma unroll 16
    for (int d = 0; d < 128; ++d) acc += sx[w][d] * Wp[d * 32];
    float h = acc;
    sh[w][lane] = h;
    __syncwarp();

    float hm = 0.f;
#pragma unroll
    for (int k = 0; k < 32; ++k) hm += sh[w][k] * linW[k * 32 + lane];
    g_hm[(size_t)node * 32 + lane] = hm;

    float pi0 = h * attW[lane * 2 + 0];
    float pi1 = h * attW[lane * 2 + 1];
    float pj0 = h * attW[(32 + lane) * 2 + 0];
    float pj1 = h * attW[(32 + lane) * 2 + 1];
#pragma unroll
    for (int off = 16; off; off >>= 1) {
        pi0 += __shfl_down_sync(0xffffffffu, pi0, off);
        pi1 += __shfl_down_sync(0xffffffffu, pi1, off);
        pj0 += __shfl_down_sync(0xffffffffu, pj0, off);
        pj1 += __shfl_down_sync(0xffffffffu, pj1, off);
    }
    if (lane == 0) {
        g_ai[node] = make_float2(pi0, pi1);
        g_aj[node] = make_float2(pj0, pj1);
    }
}

// ---------------- K2: degree histogram with rank capture (4-way split) ----------------
__global__ void k_cnt(const int* __restrict__ dst, int e_total, int n) {
    int i = blockIdx.x * 256 + threadIdx.x;
    unsigned c = ((threadIdx.x >> 5) & 3);
    int cb = c * n;
    int base = i * 4;
    if (base + 4 <= e_total) {
        int4 d = *(const int4*)(dst + base);
        unsigned r0 = atomicAdd(&g_cnt4[cb + d.x], 1);
        unsigned r1 = atomicAdd(&g_cnt4[cb + d.y], 1);
        unsigned r2 = atomicAdd(&g_cnt4[cb + d.z], 1);
        unsigned r3 = atomicAdd(&g_cnt4[cb + d.w], 1);
        uint4 rr = make_uint4((c << 28) | r0, (c << 28) | r1, (c << 28) | r2, (c << 28) | r3);
        *(uint4*)(g_rank + base) = rr;
    } else {
        for (int e = base; e < e_total; ++e) {
            unsigned r = atomicAdd(&g_cnt4[cb + dst[e]], 1);
            g_rank[e] = (c << 28) | r;
        }
    }
}

// ---------------- K3: scan ----------------
__global__ void k_scan1(int n) {
    __shared__ int s[1024];
    int i = blockIdx.x * 1024 + threadIdx.x;
    int v = 0;
    if (i < n) {
        v = g_cnt4[i] + g_cnt4[n + i] + g_cnt4[2 * n + i] + g_cnt4[3 * n + i];
        g_cnt[i] = v;
    }
    s[threadIdx.x] = v;
    __syncthreads();
    for (int off = 1; off < 1024; off <<= 1) {
        int t = (threadIdx.x >= off) ? s[threadIdx.x - off] : 0;
        __syncthreads();
        s[threadIdx.x] += t;
        __syncthreads();
    }
    if (i < n) g_scan[i] = s[threadIdx.x];
    if (threadIdx.x == 1023) g_bsum[blockIdx.x] = s[1023];
}
__global__ void k_scan3(int n) {
    __shared__ int soff;
    int tid = threadIdx.x;
    if (tid < 32) {
        int bid = blockIdx.x;
        int v = (tid < bid) ? g_bsum[tid] : 0;
        if (tid + 32 < bid) v += g_bsum[tid + 32];
#pragma unroll
        for (int off = 16; off; off >>= 1) v += __shfl_down_sync(0xffffffffu, v, off);
        if (tid == 0) soff = v;
    }
    __syncthreads();
    int i = blockIdx.x * 1024 + tid;
    if (i < n) {
        int c0 = g_cnt4[i], c1 = g_cnt4[n + i], c2 = g_cnt4[2 * n + i];
        int rp = g_scan[i] - g_cnt[i] + soff;
        g_rowptr[i] = rp;
        g_cnt4[i] = rp;
        g_cnt4[n + i] = rp + c0;
        g_cnt4[2 * n + i] = rp + c0 + c1;
        g_cnt4[3 * n + i] = rp + c0 + c1 + c2;
    }
}

// ---------------- K4: edge pass — ea, exp(alpha); scatter 48B record, no atomics ----------------
__global__ __launch_bounds__(256) void k_edge1(
    const int* __restrict__ ei, const int* __restrict__ etypes,
    const float* __restrict__ eattr, const float* __restrict__ cW,
    const float* __restrict__ attW, int e_total, int n)
{
    __shared__ float4 scW4[64];
    __shared__ float2 saW2[16];
    __shared__ float  sae[8];
    int tid = threadIdx.x;
    if (tid < 64) scW4[tid] = ((const float4*)cW)[tid];
    else if (tid < 80) saW2[tid - 64] = ((const float2*)(attW + 160))[tid - 64];
    else if (tid < 88) sae[tid - 80] = g_ae[tid - 80];
    __syncthreads();

    int e = blockIdx.x * 256 + tid;
    if (e >= e_total) return;
    int src = ei[e], dst = ei[e_total + e], et = etypes[e];

    const float4* er = (const float4*)(eattr + (size_t)e * 16);
    float4 q0 = er[0], q1 = er[1], q2 = er[2], q3 = er[3];
    float va[16] = {q0.x, q0.y, q0.z, q0.w, q1.x, q1.y, q1.z, q1.w,
                    q2.x, q2.y, q2.z, q2.w, q3.x, q3.y, q3.z, q3.w};

    float ea[16];
#pragma unroll
    for (int k = 0; k < 16; ++k) ea[k] = 0.f;
#pragma unroll
    for (int d = 0; d < 16; ++d) {
        float vd = va[d];
#pragma unroll
        for (int k4 = 0; k4 < 4; ++k4) {
            float4 w = scW4[d * 4 + k4];
            ea[k4 * 4 + 0] += vd * w.x;
            ea[k4 * 4 + 1] += vd * w.y;
            ea[k4 * 4 + 2] += vd * w.z;
            ea[k4 * 4 + 3] += vd * w.w;
        }
    }
#pragma unroll
    for (int k = 0; k < 16; ++k) ea[k] = lrelu(ea[k]);

    float2 fi = g_ai[dst], fj = g_aj[src];
    float a0 = fi.x + fj.x + sae[et * 2 + 0];
    float a1 = fi.y + fj.y + sae[et * 2 + 1];
#pragma unroll
    for (int k = 0; k < 16; ++k) {
        float2 w = saW2[k];
        a0 += ea[k] * w.x;
        a1 += ea[k] * w.y;
    }
    float e0 = __expf(lrelu(a0));
    float e1 = __expf(lrelu(a1));

    uint32_t u[8];
#pragma unroll
    for (int i2 = 0; i2 < 8; ++i2) {
        __half2 h = __floats2half2_rn(ea[2 * i2], ea[2 * i2 + 1]);
        u[i2] = *reinterpret_cast<uint32_t*>(&h);
    }

    unsigned pk = g_rank[e];
    int pos = g_cnt4[(pk >> 28) * n + dst] + (int)(pk & 0x0FFFFFFFu);
    float4* rp = (float4*)(g_rec + (size_t)pos * RECF);
    rp[0] = make_float4(__int_as_float(src), e0, e1, 0.f);
    rp[1] = make_float4(__uint_as_float(u[0]), __uint_as_float(u[1]),
                        __uint_as_float(u[2]), __uint_as_float(u[3]));
    rp[2] = make_float4(__uint_as_float(u[4]), __uint_as_float(u[5]),
                        __uint_as_float(u[6]), __uint_as_float(u[7]));
}

// ---------------- K5: aggregate — interleaved persistent warps ----------------
__global__ __launch_bounds__(256) void k_edge2(
    float* __restrict__ out, const float* __restrict__ linW, int n)
{
    __shared__ float slW2[512];
    __shared__ float ss0[8][32];
    __shared__ float ss1[8][32];
    int tid = threadIdx.x;
    slW2[tid] = linW[1024 + tid];
    slW2[256 + tid] = linW[1280 + tid];
    __syncthreads();

    int w = tid >> 5, lane = tid & 31;
    int wid = blockIdx.x * 8 + w;
    int W = gridDim.x * 8;

    int loff = (lane < 16) ? lane : (lane - 16) + RECF;
    bool lact = (lane & 15) < RECF;

    for (int node = wid; node < n; node += W) {
        int beg = g_rowptr[node];
        int cnt = g_cnt[node];
        const float* rb = g_rec + (size_t)beg * RECF;

        float acc0 = 0.f, acc1 = 0.f;
        float s0x = 0.f, s0y = 0.f, s1x = 0.f, s1y = 0.f;
        float den0 = 0.f, den1 = 0.f;

        int p = 0;
#pragma unroll 2
        for (; p + 2 <= cnt; p += 2) {
            float v = lact ? rb[(size_t)p * RECF + loff] : 0.f;

            int   sa = __float_as_int(__shfl_sync(0xffffffffu, v, 0));
            float a0 = __shfl_sync(0xffffffffu, v, 1);
            float a1 = __shfl_sync(0xffffffffu, v, 2);
            int   sb = __float_as_int(__shfl_sync(0xffffffffu, v, 16));
            float b0 = __shfl_sync(0xffffffffu, v, 17);
            float b1 = __shfl_sync(0xffffffffu, v, 18);

            __half2 hh = *reinterpret_cast<__half2*>(&v);
            float2 f2 = __half22float2(hh);
            float e0s = (lane < 16) ? a0 : b0;
            float e1s = (lane < 16) ? a1 : b1;
            s0x += e0s * f2.x; s0y += e0s * f2.y;
            s1x += e1s * f2.x; s1y += e1s * f2.y;

            float ha = g_hm[(size_t)sa * 32 + lane];
            float hb = g_hm[(size_t)sb * 32 + lane];
            acc0 += a0 * ha + b0 * hb;
            acc1 += a1 * ha + b1 * hb;
            den0 += a0 + b0;
            den1 += a1 + b1;
        }
        if (p < cnt) {
            float v = (lane < RECF) ? rb[(size_t)p * RECF + lane] : 0.f;
            int   sa = __float_as_int(__shfl_sync(0xffffffffu, v, 0));
            float a0 = __shfl_sync(0xffffffffu, v, 1);
            float a1 = __shfl_sync(0xffffffffu, v, 2);
            __half2 hh = *reinterpret_cast<__half2*>(&v);
            float2 f2 = __half22float2(hh);
            if (lane < 16) {
                s0x += a0 * f2.x; s0y += a0 * f2.y;
                s1x += a1 * f2.x; s1y += a1 * f2.y;
            }
            float ha = g_hm[(size_t)sa * 32 + lane];
            acc0 += a0 * ha;
            acc1 += a1 * ha;
            den0 += a0;
            den1 += a1;
        }

        if (lane >= 4 && lane < 12) {
            int d = (lane - 4) * 2;
            ss0[w][d] = s0x; ss0[w][d + 1] = s0y;
            ss1[w][d] = s1x; ss1[w][d + 1] = s1y;
        } else if (lane >= 20 && lane < 28) {
            int d = 16 + (lane - 20) * 2;
            ss0[w][d] = s0x; ss0[w][d + 1] = s0y;
            ss1[w][d] = s1x; ss1[w][d + 1] = s1y;
        }
        __syncwarp();

#pragma unroll
        for (int k = 0; k < 16; ++k) {
            float lw = slW2[k * 32 + lane];
            acc0 += (ss0[w][k] + ss0[w][16 + k]) * lw;
            acc1 += (ss1[w][k] + ss1[w][16 + k]) * lw;
        }
        __syncwarp();

        float i0 = (den0 != 0.f) ? 1.f / den0 : 0.f;
        float i1 = (den1 != 0.f) ? 1.f / den1 : 0.f;
        out[(size_t)node * 64 + lane]      = fmaxf(acc0 * i0, 0.f);
        out[(size_t)node * 64 + 32 + lane] = fmaxf(acc1 * i1, 0.f);
    }
}

// ---------------- launch ----------------
extern "C" void kernel_launch(void* const* d_in, const int* in_sizes, int n_in,
                              void* d_out, int out_size)
{
    const float* x      = (const float*)d_in[0];
    const int*   ei     = (const int*)  d_in[1];
    const int*   ntypes = (const int*)  d_in[2];
    const int*   etypes = (const int*)  d_in[3];
    const float* eattr  = (const float*)d_in[4];
    const float* hetW   = (const float*)d_in[5];
    const float* hetB   = (const float*)d_in[6];
    const float* ett    = (const float*)d_in[7];
    const float* cW     = (const float*)d_in[8];
    const float* attW   = (const float*)d_in[9];
    const float* linW   = (const float*)d_in[10];

    int n = in_sizes[0] / 128;
    int e = in_sizes[1] / 2;
    if (n > NMAX) n = NMAX;
    if (e > EMAX) e = EMAX;

    k_node<<<(n + 7) / 8, 256>>>(x, ntypes, hetW, hetB, attW, linW, ett, n);
    k_cnt<<<((e + 3) / 4 + 255) / 256, 256>>>(ei + e, e, n);

    int nb = (n + 1023) / 1024;
    k_scan1<<<nb, 1024>>>(n);
    k_scan3<<<nb, 1024>>>(n);

    k_edge1<<<(e + 255) / 256, 256>>>(ei, etypes, eattr, cW, attW, e, n);
    k_edge2<<<592, 256>>>((float*)d_out, linW, n);
}

// round 7
// speedup vs baseline: 1.0794x; 1.0710x over previous
#include <cuda_runtime.h>
#include <cuda_fp16.h>
#include <cstdint>

#define NMAX 50000
#define EMAX 1600000
#define RECF 12   // floats per CSR record: src,e0,e1,pad, 8x half2 (ea[16] fp16)

// ---------------- scratch (static __device__, no allocations) ----------------
__device__ float  g_hm[NMAX * 32];            // h @ lin_W[0:32] per node (6.4MB, L2-resident)
__device__ float2 g_ai[NMAX];                 // h @ att_W[0:32]  (dst term)
__device__ float2 g_aj[NMAX];                 // h @ att_W[32:64] (src term)
__device__ float  g_rec[(size_t)EMAX * RECF]; // CSR records (76.8MB)
__device__ int    g_cnt4[4 * NMAX];           // split histogram
__device__ int    g_cnt[NMAX];
__device__ int    g_rowptr[NMAX];
__device__ int    g_cur[NMAX];
__device__ float  g_ae[8];                    // lrelu(etype_table) @ att_W[64:80]
__device__ int    g_pub[64];                  // lookback: (value<<2)|state
__device__ int    g_tilectr;

__device__ __forceinline__ float lrelu(float v) { return v > 0.f ? v : 0.2f * v; }

// ---------------- K1: node precompute (warp per node) + folded resets ----------------
__global__ __launch_bounds__(256) void k_node(
    const float* __restrict__ x, const int* __restrict__ ntypes,
    const float* __restrict__ hetW, const float* __restrict__ hetB,
    const float* __restrict__ attW, const float* __restrict__ linW,
    const float* __restrict__ ett, int n)
{
    __shared__ float sx[8][128];
    __shared__ float sh[8][32];
    int tid = threadIdx.x;

    // folded: zero split histogram
    int z = blockIdx.x * 256 + tid;
    if (z < 4 * n) g_cnt4[z] = 0;
    // folded: scan state reset + per-etype attention term
    if (blockIdx.x == 0) {
        if (tid < 64) g_pub[tid] = 0;
        if (tid == 64) g_tilectr = 0;
        if (tid < 8) {
            int t = tid >> 1, hh = tid & 1;
            float s = 0.f;
            for (int k = 0; k < 16; ++k)
                s += lrelu(ett[t * 16 + k]) * attW[(64 + k) * 2 + hh];
            g_ae[tid] = s;
        }
    }

    int w = tid >> 5, lane = tid & 31;
    int node = blockIdx.x * 8 + w;
    if (node >= n) return;

    const float4* xr = (const float4*)(x + (size_t)node * 128);
    ((float4*)sx[w])[lane] = xr[lane];
    __syncwarp();

    int t = ntypes[node];
    const float* Wp = hetW + (size_t)t * 4096 + lane;
    float acc = hetB[t * 32 + lane];
#pragma unroll 16
    for (int d = 0; d < 128; ++d) acc += sx[w][d] * Wp[d * 32];
    float h = acc;
    sh[w][lane] = h;
    __syncwarp();

    float hm = 0.f;
#pragma unroll
    for (int k = 0; k < 32; ++k) hm += sh[w][k] * linW[k * 32 + lane];
    g_hm[(size_t)node * 32 + lane] = hm;

    float pi0 = h * attW[lane * 2 + 0];
    float pi1 = h * attW[lane * 2 + 1];
    float pj0 = h * attW[(32 + lane) * 2 + 0];
    float pj1 = h * attW[(32 + lane) * 2 + 1];
#pragma unroll
    for (int off = 16; off; off >>= 1) {
        pi0 += __shfl_down_sync(0xffffffffu, pi0, off);
        pi1 += __shfl_down_sync(0xffffffffu, pi1, off);
        pj0 += __shfl_down_sync(0xffffffffu, pj0, off);
        pj1 += __shfl_down_sync(0xffffffffu, pj1, off);
    }
    if (lane == 0) {
        g_ai[node] = make_float2(pi0, pi1);
        g_aj[node] = make_float2(pj0, pj1);
    }
}

// ---------------- K2: degree histogram, 4-way split counters ----------------
__global__ void k_cnt(const int* __restrict__ dst, int e_total, int n) {
    int i = blockIdx.x * 256 + threadIdx.x;
    int c = ((threadIdx.x >> 5) & 3) * n;
    int base = i * 4;
    if (base + 4 <= e_total) {
        int4 d = *(const int4*)(dst + base);
        atomicAdd(&g_cnt4[c + d.x], 1);
        atomicAdd(&g_cnt4[c + d.y], 1);
        atomicAdd(&g_cnt4[c + d.z], 1);
        atomicAdd(&g_cnt4[c + d.w], 1);
    } else {
        for (int e = base; e < e_total; ++e) atomicAdd(&g_cnt4[c + dst[e]], 1);
    }
}

// ---------------- K3: single-pass decoupled-lookback scan ----------------
__global__ __launch_bounds__(1024) void k_scan(int n) {
    __shared__ int s[1024];
    __shared__ int sexcl;
    __shared__ int stile;
    int tid = threadIdx.x;
    if (tid == 0) stile = atomicAdd(&g_tilectr, 1);
    __syncthreads();
    int tile = stile;
    int i = tile * 1024 + tid;

    int v = 0;
    if (i < n) {
        v = g_cnt4[i] + g_cnt4[n + i] + g_cnt4[2 * n + i] + g_cnt4[3 * n + i];
        g_cnt[i] = v;
    }
    s[tid] = v;
    __syncthreads();
    for (int off = 1; off < 1024; off <<= 1) {
        int t = (tid >= off) ? s[tid - off] : 0;
        __syncthreads();
        s[tid] += t;
        __syncthreads();
    }

    if (tid == 0) {
        int total = s[1023];
        int excl = 0;
        if (tile == 0) {
            atomicExch(&g_pub[0], (total << 2) | 2);
        } else {
            atomicExch(&g_pub[tile], (total << 2) | 1);
            int j = tile - 1;
            while (j >= 0) {
                int p;
                do { p = atomicAdd(&g_pub[j], 0); } while ((p & 3) == 0);
                excl += p >> 2;
                if ((p & 3) == 2) break;
                --j;
            }
            atomicExch(&g_pub[tile], ((excl + total) << 2) | 2);
        }
        sexcl = excl;
    }
    __syncthreads();
    int excl = sexcl;
    if (i < n) {
        g_rowptr[i] = excl + s[tid] - v;
        g_cur[i] = 0;
    }
}

// ---------------- K4: edge pass — ea, exp(alpha); scatter 48B record in CSR order ----------------
__global__ __launch_bounds__(256) void k_edge1(
    const int* __restrict__ ei, const int* __restrict__ etypes,
    const float* __restrict__ eattr, const float* __restrict__ cW,
    const float* __restrict__ attW, int e_total)
{
    __shared__ float4 scW4[64];
    __shared__ float2 saW2[16];
    __shared__ float  sae[8];
    int tid = threadIdx.x;
    if (tid < 64) scW4[tid] = ((const float4*)cW)[tid];
    else if (tid < 80) saW2[tid - 64] = ((const float2*)(attW + 160))[tid - 64];
    else if (tid < 88) sae[tid - 80] = g_ae[tid - 80];
    __syncthreads();

    int e = blockIdx.x * 256 + tid;
    if (e >= e_total) return;
    int src = ei[e], dst = ei[e_total + e], et = etypes[e];

    const float4* er = (const float4*)(eattr + (size_t)e * 16);
    float4 q0 = er[0], q1 = er[1], q2 = er[2], q3 = er[3];
    float va[16] = {q0.x, q0.y, q0.z, q0.w, q1.x, q1.y, q1.z, q1.w,
                    q2.x, q2.y, q2.z, q2.w, q3.x, q3.y, q3.z, q3.w};

    float ea[16];
#pragma unroll
    for (int k = 0; k < 16; ++k) ea[k] = 0.f;
#pragma unroll
    for (int d = 0; d < 16; ++d) {
        float vd = va[d];
#pragma unroll
        for (int k4 = 0; k4 < 4; ++k4) {
            float4 w = scW4[d * 4 + k4];
            ea[k4 * 4 + 0] += vd * w.x;
            ea[k4 * 4 + 1] += vd * w.y;
            ea[k4 * 4 + 2] += vd * w.z;
            ea[k4 * 4 + 3] += vd * w.w;
        }
    }
#pragma unroll
    for (int k = 0; k < 16; ++k) ea[k] = lrelu(ea[k]);

    float2 fi = g_ai[dst], fj = g_aj[src];
    float a0 = fi.x + fj.x + sae[et * 2 + 0];
    float a1 = fi.y + fj.y + sae[et * 2 + 1];
#pragma unroll
    for (int k = 0; k < 16; ++k) {
        float2 w = saW2[k];
        a0 += ea[k] * w.x;
        a1 += ea[k] * w.y;
    }
    float e0 = __expf(lrelu(a0));
    float e1 = __expf(lrelu(a1));

    uint32_t u[8];
#pragma unroll
    for (int i2 = 0; i2 < 8; ++i2) {
        __half2 h = __floats2half2_rn(ea[2 * i2], ea[2 * i2 + 1]);
        u[i2] = *reinterpret_cast<uint32_t*>(&h);
    }

    int pos = g_rowptr[dst] + atomicAdd(&g_cur[dst], 1);
    float4* rp = (float4*)(g_rec + (size_t)pos * RECF);
    rp[0] = make_float4(__int_as_float(src), e0, e1, 0.f);
    rp[1] = make_float4(__uint_as_float(u[0]), __uint_as_float(u[1]),
                        __uint_as_float(u[2]), __uint_as_float(u[3]));
    rp[2] = make_float4(__uint_as_float(u[4]), __uint_as_float(u[5]),
                        __uint_as_float(u[6]), __uint_as_float(u[7]));
}

// ---------------- K5: aggregate — warp per dst node ----------------
__global__ __launch_bounds__(256) void k_edge2(
    float* __restrict__ out, const float* __restrict__ linW, int n)
{
    __shared__ float slW2[512];
    __shared__ float ss0[8][32];
    __shared__ float ss1[8][32];
    int tid = threadIdx.x;
    slW2[tid] = linW[1024 + tid];
    slW2[256 + tid] = linW[1280 + tid];
    __syncthreads();

    int w = tid >> 5, lane = tid & 31;
    int node = blockIdx.x * 8 + w;
    if (node >= n) return;

    int beg = g_rowptr[node];
    int cnt = g_cnt[node];
    const float* rb = g_rec + (size_t)beg * RECF;

    float acc0 = 0.f, acc1 = 0.f;
    float s0x = 0.f, s0y = 0.f, s1x = 0.f, s1y = 0.f;
    float den0 = 0.f, den1 = 0.f;

    int loff = (lane < 16) ? lane : (lane - 16) + RECF;
    bool lact = (lane & 15) < RECF;

    int p = 0;
#pragma unroll 2
    for (; p + 2 <= cnt; p += 2) {
        float v = lact ? rb[(size_t)p * RECF + loff] : 0.f;

        int   sa = __float_as_int(__shfl_sync(0xffffffffu, v, 0));
        float a0 = __shfl_sync(0xffffffffu, v, 1);
        float a1 = __shfl_sync(0xffffffffu, v, 2);
        int   sb = __float_as_int(__shfl_sync(0xffffffffu, v, 16));
        float b0 = __shfl_sync(0xffffffffu, v, 17);
        float b1 = __shfl_sync(0xffffffffu, v, 18);

        __half2 hh = *reinterpret_cast<__half2*>(&v);
        float2 f2 = __half22float2(hh);
        float e0s = (lane < 16) ? a0 : b0;
        float e1s = (lane < 16) ? a1 : b1;
        s0x += e0s * f2.x; s0y += e0s * f2.y;
        s1x += e1s * f2.x; s1y += e1s * f2.y;

        float ha = g_hm[(size_t)sa * 32 + lane];
        float hb = g_hm[(size_t)sb * 32 + lane];
        acc0 += a0 * ha + b0 * hb;
        acc1 += a1 * ha + b1 * hb;
        den0 += a0 + b0;
        den1 += a1 + b1;
    }
    if (p < cnt) {
        float v = (lane < RECF) ? rb[(size_t)p * RECF + lane] : 0.f;
        int   sa = __float_as_int(__shfl_sync(0xffffffffu, v, 0));
        float a0 = __shfl_sync(0xffffffffu, v, 1);
        float a1 = __shfl_sync(0xffffffffu, v, 2);
        __half2 hh = *reinterpret_cast<__half2*>(&v);
        float2 f2 = __half22float2(hh);
        if (lane < 16) {
            s0x += a0 * f2.x; s0y += a0 * f2.y;
            s1x += a1 * f2.x; s1y += a1 * f2.y;
        }
        float ha = g_hm[(size_t)sa * 32 + lane];
        acc0 += a0 * ha;
        acc1 += a1 * ha;
        den0 += a0;
        den1 += a1;
    }

    if (lane >= 4 && lane < 12) {
        int d = (lane - 4) * 2;
        ss0[w][d] = s0x; ss0[w][d + 1] = s0y;
        ss1[w][d] = s1x; ss1[w][d + 1] = s1y;
    } else if (lane >= 20 && lane < 28) {
        int d = 16 + (lane - 20) * 2;
        ss0[w][d] = s0x; ss0[w][d + 1] = s0y;
        ss1[w][d] = s1x; ss1[w][d + 1] = s1y;
    }
    __syncwarp();

#pragma unroll
    for (int k = 0; k < 16; ++k) {
        float lw = slW2[k * 32 + lane];
        acc0 += (ss0[w][k] + ss0[w][16 + k]) * lw;
        acc1 += (ss1[w][k] + ss1[w][16 + k]) * lw;
    }

    float i0 = (den0 != 0.f) ? 1.f / den0 : 0.f;
    float i1 = (den1 != 0.f) ? 1.f / den1 : 0.f;
    out[(size_t)node * 64 + lane]      = fmaxf(acc0 * i0, 0.f);
    out[(size_t)node * 64 + 32 + lane] = fmaxf(acc1 * i1, 0.f);
}

// ---------------- launch ----------------
extern "C" void kernel_launch(void* const* d_in, const int* in_sizes, int n_in,
                              void* d_out, int out_size)
{
    const float* x      = (const float*)d_in[0];
    const int*   ei     = (const int*)  d_in[1];
    const int*   ntypes = (const int*)  d_in[2];
    const int*   etypes = (const int*)  d_in[3];
    const float* eattr  = (const float*)d_in[4];
    const float* hetW   = (const float*)d_in[5];
    const float* hetB   = (const float*)d_in[6];
    const float* ett    = (const float*)d_in[7];
    const float* cW     = (const float*)d_in[8];
    const float* attW   = (const float*)d_in[9];
    const float* linW   = (const float*)d_in[10];

    int n = in_sizes[0] / 128;
    int e = in_sizes[1] / 2;
    if (n > NMAX) n = NMAX;
    if (e > EMAX) e = EMAX;

    k_node<<<(n + 7) / 8, 256>>>(x, ntypes, hetW, hetB, attW, linW, ett, n);
    k_cnt<<<(e / 4 + 255) / 256, 256>>>(ei + e, e, n);
    k_scan<<<(n + 1023) / 1024, 1024>>>(n);
    k_edge1<<<(e + 255) / 256, 256>>>(ei, etypes, eattr, cW, attW, e);
    k_edge2<<<(n + 7) / 8, 256>>>((float*)d_out, linW, n);
}

// round 8
// speedup vs baseline: 1.2393x; 1.1481x over previous
#include <cuda_runtime.h>
#include <cuda_fp16.h>
#include <cstdint>

#define NMAX 50000
#define EMAX 1600000
#define RECF 12   // floats per CSR record: src,e0,e1,pad, 8x half2 (ea[16] fp16)

// ---------------- scratch (static __device__, zero-initialized at load) ----------------
__device__ float  g_hm[NMAX * 32];            // h @ lin_W[0:32] per node (6.4MB, L2-resident)
__device__ float2 g_ai[NMAX];                 // h @ att_W[0:32]  (dst term)
__device__ float2 g_aj[NMAX];                 // h @ att_W[32:64] (src term)
__device__ float  g_rec[(size_t)EMAX * RECF]; // CSR records (76.8MB)
__device__ int    g_cnt4[4 * NMAX];           // split histogram (zero at k_node entry; re-zeroed by k_scan)
__device__ int    g_cnt[NMAX];
__device__ int    g_rowptr[NMAX];
__device__ int    g_cur[NMAX];                // zeroed by k_scan each run
__device__ float  g_ae[8];                    // lrelu(etype_table) @ att_W[64:80]
__device__ int    g_pub[64];                  // lookback state (zeroed by k_edge1 for next run)
__device__ int    g_tilectr;                  // (zeroed by k_edge1 for next run)

__device__ __forceinline__ float lrelu(float v) { return v > 0.f ? v : 0.2f * v; }

// ---------------- K1: node precompute (warp per node) + edge histogram + ae ----------------
// Precondition: g_cnt4 is all-zero (static init on first call; k_scan re-zeroes for later calls).
__global__ __launch_bounds__(256) void k_node(
    const float* __restrict__ x, const int* __restrict__ ntypes,
    const float* __restrict__ hetW, const float* __restrict__ hetB,
    const float* __restrict__ attW, const float* __restrict__ linW,
    const float* __restrict__ ett, const int* __restrict__ dst, int n, int e)
{
    __shared__ float sx[8][128];
    __shared__ float sh[8][32];
    int tid = threadIdx.x;

    // folded: per-etype attention term
    if (blockIdx.x == 0 && tid < 8) {
        int t = tid >> 1, hh = tid & 1;
        float s = 0.f;
        for (int k = 0; k < 16; ++k)
            s += lrelu(ett[t * 16 + k]) * attW[(64 + k) * 2 + hh];
        g_ae[tid] = s;
    }

    // folded: degree histogram over dst (4-way split counters)
    {
        int i4 = blockIdx.x * 256 + tid;
        int c = ((tid >> 5) & 3) * n;
        int base = i4 * 4;
        if (base + 4 <= e) {
            int4 d = *(const int4*)(dst + base);
            atomicAdd(&g_cnt4[c + d.x], 1);
            atomicAdd(&g_cnt4[c + d.y], 1);
            atomicAdd(&g_cnt4[c + d.z], 1);
            atomicAdd(&g_cnt4[c + d.w], 1);
        } else if (base < e) {
            for (int q = base; q < e; ++q) atomicAdd(&g_cnt4[c + dst[q]], 1);
        }
    }

    int w = tid >> 5, lane = tid & 31;
    int node = blockIdx.x * 8 + w;
    if (node >= n) return;

    const float4* xr = (const float4*)(x + (size_t)node * 128);
    ((float4*)sx[w])[lane] = xr[lane];
    __syncwarp();

    int t = ntypes[node];
    const float* Wp = hetW + (size_t)t * 4096 + lane;
    float acc = hetB[t * 32 + lane];
#pragma unroll 16
    for (int d = 0; d < 128; ++d) acc += sx[w][d] * Wp[d * 32];
    float h = acc;
    sh[w][lane] = h;
    __syncwarp();

    float hm = 0.f;
#pragma unroll
    for (int k = 0; k < 32; ++k) hm += sh[w][k] * linW[k * 32 + lane];
    g_hm[(size_t)node * 32 + lane] = hm;

    float pi0 = h * attW[lane * 2 + 0];
    float pi1 = h * attW[lane * 2 + 1];
    float pj0 = h * attW[(32 + lane) * 2 + 0];
    float pj1 = h * attW[(32 + lane) * 2 + 1];
#pragma unroll
    for (int off = 16; off; off >>= 1) {
        pi0 += __shfl_down_sync(0xffffffffu, pi0, off);
        pi1 += __shfl_down_sync(0xffffffffu, pi1, off);
        pj0 += __shfl_down_sync(0xffffffffu, pj0, off);
        pj1 += __shfl_down_sync(0xffffffffu, pj1, off);
    }
    if (lane == 0) {
        g_ai[node] = make_float2(pi0, pi1);
        g_aj[node] = make_float2(pj0, pj1);
    }
}

// ---------------- K2: single-pass decoupled-lookback scan (+ re-zero cnt4, cur) ----------------
__global__ __launch_bounds__(1024) void k_scan(int n) {
    __shared__ int s[1024];
    __shared__ int sexcl;
    __shared__ int stile;
    int tid = threadIdx.x;
    if (tid == 0) stile = atomicAdd(&g_tilectr, 1);
    __syncthreads();
    int tile = stile;
    int i = tile * 1024 + tid;

    int v = 0;
    if (i < n) {
        v = g_cnt4[i] + g_cnt4[n + i] + g_cnt4[2 * n + i] + g_cnt4[3 * n + i];
        g_cnt[i] = v;
        // re-zero for the NEXT kernel_launch invocation (graph replay safe)
        g_cnt4[i] = 0; g_cnt4[n + i] = 0; g_cnt4[2 * n + i] = 0; g_cnt4[3 * n + i] = 0;
    }
    s[tid] = v;
    __syncthreads();
    for (int off = 1; off < 1024; off <<= 1) {
        int t = (tid >= off) ? s[tid - off] : 0;
        __syncthreads();
        s[tid] += t;
        __syncthreads();
    }

    if (tid == 0) {
        int total = s[1023];
        int excl = 0;
        if (tile == 0) {
            atomicExch(&g_pub[0], (total << 2) | 2);
        } else {
            atomicExch(&g_pub[tile], (total << 2) | 1);
            int j = tile - 1;
            while (j >= 0) {
                int p;
                do { p = atomicAdd(&g_pub[j], 0); } while ((p & 3) == 0);
                excl += p >> 2;
                if ((p & 3) == 2) break;
                --j;
            }
            atomicExch(&g_pub[tile], ((excl + total) << 2) | 2);
        }
        sexcl = excl;
    }
    __syncthreads();
    int excl = sexcl;
    if (i < n) {
        g_rowptr[i] = excl + s[tid] - v;
        g_cur[i] = 0;
    }
}

// ---------------- K3: edge pass — fp16 ea, exp(alpha); scatter 48B record ----------------
__global__ __launch_bounds__(256) void k_edge1(
    const int* __restrict__ ei, const int* __restrict__ etypes,
    const float* __restrict__ eattr, const float* __restrict__ cW,
    const float* __restrict__ attW, int e_total)
{
    __shared__ float4 scWh4[32];   // cW packed half2: row d -> 2 float4 (8 half2 = 16 cols)
    __shared__ float2 saW2[16];    // att_W rows 80..95 (fp32)
    __shared__ float  sae[8];
    int tid = threadIdx.x;

    // reset lookback scan state for the NEXT invocation
    if (blockIdx.x == 0) {
        if (tid < 64) g_pub[tid] = 0;
        if (tid == 64) g_tilectr = 0;
    }

    if (tid < 32) {
        int d = tid >> 1, hsel = tid & 1;
        float4 qa = ((const float4*)cW)[d * 4 + hsel * 2];
        float4 qb = ((const float4*)cW)[d * 4 + hsel * 2 + 1];
        __half2 h0 = __floats2half2_rn(qa.x, qa.y);
        __half2 h1 = __floats2half2_rn(qa.z, qa.w);
        __half2 h2 = __floats2half2_rn(qb.x, qb.y);
        __half2 h3 = __floats2half2_rn(qb.z, qb.w);
        float4 packed;
        ((__half2*)&packed)[0] = h0; ((__half2*)&packed)[1] = h1;
        ((__half2*)&packed)[2] = h2; ((__half2*)&packed)[3] = h3;
        scWh4[tid] = packed;
    } else if (tid < 48) saW2[tid - 32] = ((const float2*)(attW + 160))[tid - 32];
    else if (tid < 56) sae[tid - 48] = g_ae[tid - 48];
    __syncthreads();

    int e = blockIdx.x * 256 + tid;
    if (e >= e_total) return;
    int src = ei[e], dst = ei[e_total + e], et = etypes[e];

    const float4* er = (const float4*)(eattr + (size_t)e * 16);
    float4 q0 = er[0], q1 = er[1], q2 = er[2], q3 = er[3];
    float va[16] = {q0.x, q0.y, q0.z, q0.w, q1.x, q1.y, q1.z, q1.w,
                    q2.x, q2.y, q2.z, q2.w, q3.x, q3.y, q3.z, q3.w};

    __half2 eh[8];
#pragma unroll
    for (int k = 0; k < 8; ++k) eh[k] = __float2half2_rn(0.f);
#pragma unroll
    for (int d = 0; d < 16; ++d) {
        __half2 vd = __float2half2_rn(va[d]);
        float4 w0 = scWh4[d * 2 + 0];
        float4 w1 = scWh4[d * 2 + 1];
        const __half2* wh0 = (const __half2*)&w0;
        const __half2* wh1 = (const __half2*)&w1;
        eh[0] = __hfma2(vd, wh0[0], eh[0]);
        eh[1] = __hfma2(vd, wh0[1], eh[1]);
        eh[2] = __hfma2(vd, wh0[2], eh[2]);
        eh[3] = __hfma2(vd, wh0[3], eh[3]);
        eh[4] = __hfma2(vd, wh1[0], eh[4]);
        eh[5] = __hfma2(vd, wh1[1], eh[5]);
        eh[6] = __hfma2(vd, wh1[2], eh[6]);
        eh[7] = __hfma2(vd, wh1[3], eh[7]);
    }
    __half2 p2 = __float2half2_rn(0.2f);
#pragma unroll
    for (int k = 0; k < 8; ++k) eh[k] = __hmax2(eh[k], __hmul2(eh[k], p2));

    // alpha dot in fp32 on the (fp16-rounded) ea — consistent with stored values
    float2 fi = g_ai[dst], fj = g_aj[src];
    float a0 = fi.x + fj.x + sae[et * 2 + 0];
    float a1 = fi.y + fj.y + sae[et * 2 + 1];
#pragma unroll
    for (int k = 0; k < 8; ++k) {
        float2 f2 = __half22float2(eh[k]);
        float2 w0 = saW2[2 * k + 0];
        float2 w1 = saW2[2 * k + 1];
        a0 += f2.x * w0.x + f2.y * w1.x;
        a1 += f2.x * w0.y + f2.y * w1.y;
    }
    float e0 = __expf(lrelu(a0));
    float e1 = __expf(lrelu(a1));

    int pos = g_rowptr[dst] + atomicAdd(&g_cur[dst], 1);
    float4* rp = (float4*)(g_rec + (size_t)pos * RECF);
    float4 r1, r2;
    ((__half2*)&r1)[0] = eh[0]; ((__half2*)&r1)[1] = eh[1];
    ((__half2*)&r1)[2] = eh[2]; ((__half2*)&r1)[3] = eh[3];
    ((__half2*)&r2)[0] = eh[4]; ((__half2*)&r2)[1] = eh[5];
    ((__half2*)&r2)[2] = eh[6]; ((__half2*)&r2)[3] = eh[7];
    rp[0] = make_float4(__int_as_float(src), e0, e1, 0.f);
    rp[1] = r1;
    rp[2] = r2;
}

// ---------------- K4: aggregate — warp per dst node, 4 records in flight ----------------
__global__ __launch_bounds__(256) void k_edge2(
    float* __restrict__ out, const float* __restrict__ linW, int n)
{
    __shared__ float slW2[512];
    __shared__ float ss0[8][32];
    __shared__ float ss1[8][32];
    int tid = threadIdx.x;
    slW2[tid] = linW[1024 + tid];
    slW2[256 + tid] = linW[1280 + tid];
    __syncthreads();

    int w = tid >> 5, lane = tid & 31;
    int node = blockIdx.x * 8 + w;
    if (node >= n) return;

    int beg = g_rowptr[node];
    int cnt = g_cnt[node];
    const float* rb = g_rec + (size_t)beg * RECF;

    float acc0 = 0.f, acc1 = 0.f;
    float s0x = 0.f, s0y = 0.f, s1x = 0.f, s1y = 0.f;
    float den0 = 0.f, den1 = 0.f;

    int loff = (lane < 16) ? lane : (lane - 16) + RECF;
    bool lact = (lane & 15) < RECF;

    int p = 0;
    for (; p + 4 <= cnt; p += 4) {
        const float* bp = rb + (size_t)p * RECF;
        float v  = lact ? bp[loff] : 0.f;        // records p, p+1
        float v2 = lact ? bp[24 + loff] : 0.f;   // records p+2, p+3

        // extract all 4 srcs first -> 4 independent hm gathers in flight
        int sa = __float_as_int(__shfl_sync(0xffffffffu, v, 0));
        int sb = __float_as_int(__shfl_sync(0xffffffffu, v, 16));
        int sc = __float_as_int(__shfl_sync(0xffffffffu, v2, 0));
        int sd = __float_as_int(__shfl_sync(0xffffffffu, v2, 16));
        float ha = g_hm[(size_t)sa * 32 + lane];
        float hb = g_hm[(size_t)sb * 32 + lane];
        float hc = g_hm[(size_t)sc * 32 + lane];
        float hd = g_hm[(size_t)sd * 32 + lane];

        float a0 = __shfl_sync(0xffffffffu, v, 1);
        float a1 = __shfl_sync(0xffffffffu, v, 2);
        float b0 = __shfl_sync(0xffffffffu, v, 17);
        float b1 = __shfl_sync(0xffffffffu, v, 18);
        float c0 = __shfl_sync(0xffffffffu, v2, 1);
        float c1 = __shfl_sync(0xffffffffu, v2, 2);
        float d0 = __shfl_sync(0xffffffffu, v2, 17);
        float d1 = __shfl_sync(0xffffffffu, v2, 18);

        __half2 hhv = *reinterpret_cast<__half2*>(&v);
        __half2 hhw = *reinterpret_cast<__half2*>(&v2);
        float2 f2 = __half22float2(hhv);
        float2 g2 = __half22float2(hhw);
        float e0s = (lane < 16) ? a0 : b0;
        float e1s = (lane < 16) ? a1 : b1;
        float e0t = (lane < 16) ? c0 : d0;
        float e1t = (lane < 16) ? c1 : d1;
        s0x += e0s * f2.x + e0t * g2.x;
        s0y += e0s * f2.y + e0t * g2.y;
        s1x += e1s * f2.x + e1t * g2.x;
        s1y += e1s * f2.y + e1t * g2.y;

        acc0 += a0 * ha + b0 * hb + c0 * hc + d0 * hd;
        acc1 += a1 * ha + b1 * hb + c1 * hc + d1 * hd;
        den0 += (a0 + b0) + (c0 + d0);
        den1 += (a1 + b1) + (c1 + d1);
    }
    if (p + 2 <= cnt) {
        float v = lact ? rb[(size_t)p * RECF + loff] : 0.f;
        int   sa = __float_as_int(__shfl_sync(0xffffffffu, v, 0));
        int   sb = __float_as_int(__shfl_sync(0xffffffffu, v, 16));
        float ha = g_hm[(size_t)sa * 32 + lane];
        float hb = g_hm[(size_t)sb * 32 + lane];
        float a0 = __shfl_sync(0xffffffffu, v, 1);
        float a1 = __shfl_sync(0xffffffffu, v, 2);
        float b0 = __shfl_sync(0xffffffffu, v, 17);
        float b1 = __shfl_sync(0xffffffffu, v, 18);
        __half2 hhv = *reinterpret_cast<__half2*>(&v);
        float2 f2 = __half22float2(hhv);
        float e0s = (lane < 16) ? a0 : b0;
        float e1s = (lane < 16) ? a1 : b1;
        s0x += e0s * f2.x; s0y += e0s * f2.y;
        s1x += e1s * f2.x; s1y += e1s * f2.y;
        acc0 += a0 * ha + b0 * hb;
        acc1 += a1 * ha + b1 * hb;
        den0 += a0 + b0;
        den1 += a1 + b1;
        p += 2;
    }
    if (p < cnt) {
        float v = (lane < RECF) ? rb[(size_t)p * RECF + lane] : 0.f;
        int   sa = __float_as_int(__shfl_sync(0xffffffffu, v, 0));
        float ha = g_hm[(size_t)sa * 32 + lane];
        float a0 = __shfl_sync(0xffffffffu, v, 1);
        float a1 = __shfl_sync(0xffffffffu, v, 2);
        __half2 hhv = *reinterpret_cast<__half2*>(&v);
        float2 f2 = __half22float2(hhv);
        if (lane < 16) {
            s0x += a0 * f2.x; s0y += a0 * f2.y;
            s1x += a1 * f2.x; s1y += a1 * f2.y;
        }
        acc0 += a0 * ha;
        acc1 += a1 * ha;
        den0 += a0;
        den1 += a1;
    }

    if (lane >= 4 && lane < 12) {
        int d = (lane - 4) * 2;
        ss0[w][d] = s0x; ss0[w][d + 1] = s0y;
        ss1[w][d] = s1x; ss1[w][d + 1] = s1y;
    } else if (lane >= 20 && lane < 28) {
        int d = 16 + (lane - 20) * 2;
        ss0[w][d] = s0x; ss0[w][d + 1] = s0y;
        ss1[w][d] = s1x; ss1[w][d + 1] = s1y;
    }
    __syncwarp();

#pragma unroll
    for (int k = 0; k < 16; ++k) {
        float lw = slW2[k * 32 + lane];
        acc0 += (ss0[w][k] + ss0[w][16 + k]) * lw;
        acc1 += (ss1[w][k] + ss1[w][16 + k]) * lw;
    }

    float i0 = (den0 != 0.f) ? 1.f / den0 : 0.f;
    float i1 = (den1 != 0.f) ? 1.f / den1 : 0.f;
    out[(size_t)node * 64 + lane]      = fmaxf(acc0 * i0, 0.f);
    out[(size_t)node * 64 + 32 + lane] = fmaxf(acc1 * i1, 0.f);
}

// ---------------- launch (4 kernels; k_edge2 at ncu's captured index 3) ----------------
extern "C" void kernel_launch(void* const* d_in, const int* in_sizes, int n_in,
                              void* d_out, int out_size)
{
    const float* x      = (const float*)d_in[0];
    const int*   ei     = (const int*)  d_in[1];
    const int*   ntypes = (const int*)  d_in[2];
    const int*   etypes = (const int*)  d_in[3];
    const float* eattr  = (const float*)d_in[4];
    const float* hetW   = (const float*)d_in[5];
    const float* hetB   = (const float*)d_in[6];
    const float* ett    = (const float*)d_in[7];
    const float* cW     = (const float*)d_in[8];
    const float* attW   = (const float*)d_in[9];
    const float* linW   = (const float*)d_in[10];

    int n = in_sizes[0] / 128;
    int e = in_sizes[1] / 2;
    if (n > NMAX) n = NMAX;
    if (e > EMAX) e = EMAX;

    k_node<<<(n + 7) / 8, 256>>>(x, ntypes, hetW, hetB, attW, linW, ett, ei + e, n, e);
    k_scan<<<(n + 1023) / 1024, 1024>>>(n);
    k_edge1<<<(e + 255) / 256, 256>>>(ei, etypes, eattr, cW, attW, e);
    k_edge2<<<(n + 7) / 8, 256>>>((float*)d_out, linW, n);
}